// round 14
// baseline (speedup 1.0000x reference)
#include <cuda_runtime.h>
#include <cuda_bf16.h>
#include <math.h>

#define Bsz 128
#define Lsz 512
#define Hsz 512
#define G3  1536
#define ICH 96
#define EPSF 1e-5f
#define NBLK 32          // persistent blocks, 16 units each
#define APITCH 72        // smem pitch (bank-conflict-free)

typedef __nv_bfloat16 bf16;

// ---------------- static device scratch ----------------
__device__ bf16  g_Xhi[(size_t)Lsz * Bsz * ICH];
__device__ bf16  g_Xlo[(size_t)Lsz * Bsz * ICH];
__device__ bf16  g_Wihi[(size_t)G3 * ICH];        // Wih0 split
__device__ bf16  g_Wilo[(size_t)G3 * ICH];
__device__ bf16  g_Wbh[3][(size_t)G3 * Hsz];      // 0:Whh0 1:Wih1 2:Whh1 (hi)
__device__ bf16  g_Wbl[3][(size_t)G3 * Hsz];      // (lo)
__device__ float g_gi0[(size_t)Lsz * Bsz * G3];   // X @ Wih0^T (no bias)
__device__ float g_Ys [(size_t)Lsz * Bsz * Hsz];  // h1 sequence [t][b][512]
__device__ bf16  g_h0hi[2][Bsz * Hsz];
__device__ bf16  g_h0lo[2][Bsz * Hsz];
__device__ bf16  g_h1hi[2][Bsz * Hsz];
__device__ bf16  g_h1lo[2][Bsz * Hsz];
__device__ float g_om[Bsz * 16], g_osd[Bsz * 16];
__device__ float g_cm[Bsz * 64], g_csd[Bsz * 64];
__device__ unsigned g_barcnt;

// ---------------- helpers ----------------
__device__ __forceinline__ void mma16816(float d[4], const unsigned a[4], const unsigned b[2]) {
    asm volatile(
        "mma.sync.aligned.m16n8k16.row.col.f32.bf16.bf16.f32 "
        "{%0,%1,%2,%3}, {%4,%5,%6,%7}, {%8,%9}, {%0,%1,%2,%3};\n"
        : "+f"(d[0]), "+f"(d[1]), "+f"(d[2]), "+f"(d[3])
        : "r"(a[0]), "r"(a[1]), "r"(a[2]), "r"(a[3]), "r"(b[0]), "r"(b[1]));
}
__device__ __forceinline__ void bf16split(float v, bf16& hi, bf16& lo) {
    hi = __float2bfloat16(v);
    lo = __float2bfloat16(v - __bfloat162float(hi));
}
#define SMU(P, o) (*(const unsigned*)&(P)[(o)])

// ---------------- RevIN normalize + split-pack ----------------
__global__ void revin_kernel(const float* __restrict__ cov,
                             const float* __restrict__ tre,
                             const float* __restrict__ outc,
                             const float* __restrict__ w_t, const float* __restrict__ b_t,
                             const float* __restrict__ w_o, const float* __restrict__ b_o,
                             const float* __restrict__ w_c, const float* __restrict__ b_c)
{
    int b  = blockIdx.x;
    int ch = threadIdx.x;            // 0..95
    const float* src; int c, nch; float w, bb;
    if (ch < 16)      { c = ch;      src = tre  + (size_t)b * Lsz * 16 + c; nch = 16; w = w_t[c]; bb = b_t[c]; }
    else if (ch < 32) { c = ch - 16; src = outc + (size_t)b * Lsz * 16 + c; nch = 16; w = w_o[c]; bb = b_o[c]; }
    else              { c = ch - 32; src = cov  + (size_t)b * Lsz * 64 + c; nch = 64; w = w_c[c]; bb = b_c[c]; }

    float sum = 0.f, sq = 0.f;
    for (int l = 0; l < Lsz; l++) {
        float v = src[(size_t)l * nch];
        sum += v; sq += v * v;
    }
    float m   = sum * (1.0f / Lsz);
    float var = (sq - sum * m) * (1.0f / (Lsz - 1));
    float s   = sqrtf(var);

    if (ch >= 16 && ch < 32) { g_om[b * 16 + c] = m; g_osd[b * 16 + c] = s; }
    else if (ch >= 32)       { g_cm[b * 64 + c] = m; g_csd[b * 64 + c] = s; }

    float inv = 1.0f / (s + EPSF);
    for (int l = 0; l < Lsz; l++) {
        float v = src[(size_t)l * nch];
        float x = (v - m) * inv * w + bb;
        bf16 hi, lo; bf16split(x, hi, lo);
        size_t o = ((size_t)l * Bsz + b) * ICH + ch;
        g_Xhi[o] = hi; g_Xlo[o] = lo;
    }
}

// ---------------- weight splitting ----------------
__global__ void wsplit0_kernel(const float* __restrict__ W)
{
    int i = blockIdx.x * blockDim.x + threadIdx.x;
    if (i < G3 * ICH) { bf16 h, l; bf16split(W[i], h, l); g_Wihi[i] = h; g_Wilo[i] = l; }
}
__global__ void wsplitB_kernel(const float* __restrict__ W, int m)
{
    int i = blockIdx.x * blockDim.x + threadIdx.x;
    if (i < G3 * Hsz) { bf16 h, l; bf16split(W[i], h, l); g_Wbh[m][i] = h; g_Wbl[m][i] = l; }
}

// ---------------- init: zero h slot0 + barrier counter ----------------
__global__ void init_kernel()
{
    int i = blockIdx.x * blockDim.x + threadIdx.x;   // 32768 (unsigned = 2 bf16)
    if (i < Bsz * Hsz / 2) {
        ((unsigned*)g_h0hi[0])[i] = 0u; ((unsigned*)g_h0lo[0])[i] = 0u;
        ((unsigned*)g_h1hi[0])[i] = 0u; ((unsigned*)g_h1lo[0])[i] = 0u;
    }
    if (i == 0) g_barcnt = 0u;
}

// ---------------- gi0 = X @ Wih0^T (mma, bf16 split) ----------------
// grid = (16 ngrp, 2 mhalf, 512 t), block = 128 (4 warps)
__global__ void __launch_bounds__(128)
gi0_kernel()
{
    __shared__ bf16 Xs[2][64][104];

    int tid = threadIdx.x;
    int wid = tid >> 5, lane = tid & 31;
    int g = lane >> 2, tg = lane & 3;
    int n0 = blockIdx.x * 96;
    int m0 = blockIdx.y * 64;
    int t  = blockIdx.z;

    for (int i = 0; i < 6; i++) {
        int idx = tid + 128 * i;
        int row = idx / 12, kq = idx % 12;
        size_t go = ((size_t)t * Bsz + m0 + row) * ICH + kq * 8;
        *(uint4*)&Xs[0][row][kq * 8] = *(const uint4*)&g_Xhi[go];
        *(uint4*)&Xs[1][row][kq * 8] = *(const uint4*)&g_Xlo[go];
    }
    __syncthreads();

    float acc[12][4];
#pragma unroll
    for (int nt = 0; nt < 12; nt++)
#pragma unroll
        for (int i = 0; i < 4; i++) acc[nt][i] = 0.f;

    int r0 = wid * 16 + g;
#pragma unroll
    for (int kk = 0; kk < 6; kk++) {
        int kb = kk * 16 + 2 * tg;
        unsigned ah[4], al[4];
        ah[0] = SMU(Xs[0][r0], kb);     ah[1] = SMU(Xs[0][r0 + 8], kb);
        ah[2] = SMU(Xs[0][r0], kb + 8); ah[3] = SMU(Xs[0][r0 + 8], kb + 8);
        al[0] = SMU(Xs[1][r0], kb);     al[1] = SMU(Xs[1][r0 + 8], kb);
        al[2] = SMU(Xs[1][r0], kb + 8); al[3] = SMU(Xs[1][r0 + 8], kb + 8);
#pragma unroll
        for (int nt = 0; nt < 12; nt++) {
            size_t wr = (size_t)(n0 + nt * 8 + g) * ICH + kk * 16 + 2 * tg;
            unsigned bh[2] = { SMU(g_Wihi, wr), SMU(g_Wihi, wr + 8) };
            unsigned bl[2] = { SMU(g_Wilo, wr), SMU(g_Wilo, wr + 8) };
            mma16816(acc[nt], ah, bh);
            mma16816(acc[nt], al, bh);
            mma16816(acc[nt], ah, bl);
        }
    }

#pragma unroll
    for (int nt = 0; nt < 12; nt++) {
        int b0  = m0 + r0;
        int col = n0 + nt * 8 + 2 * tg;
        *(float2*)&g_gi0[((size_t)t * Bsz + b0) * G3 + col]     = make_float2(acc[nt][0], acc[nt][1]);
        *(float2*)&g_gi0[((size_t)t * Bsz + b0 + 8) * G3 + col] = make_float2(acc[nt][2], acc[nt][3]);
    }
}

// ---------------- persistent RNN kernel ----------------
// grid = 32 blocks x 256 threads. Block bc owns units [16bc, 16bc+16).
// Warp wid owns batch rows [16wid, 16wid+16).
__global__ void __launch_bounds__(256)
rnn_kernel(const float* __restrict__ bih0, const float* __restrict__ bhh0,
           const float* __restrict__ bih1, const float* __restrict__ bhh1)
{
    extern __shared__ char smraw[];
    bf16* A0h = (bf16*)smraw;                 // 128 x APITCH
    bf16* A0l = A0h + 128 * APITCH;
    bf16* A1h = A0l + 128 * APITCH;
    bf16* A1l = A1h + 128 * APITCH;
    bf16* W1h = A1l + 128 * APITCH;           // 48 x APITCH
    bf16* W1l = W1h + 48 * APITCH;
    bf16* W2h = W1l + 48 * APITCH;
    bf16* W2l = W2h + 48 * APITCH;

    int tid = threadIdx.x;
    int wid = tid >> 5, lane = tid & 31;
    int g = lane >> 2, tg = lane & 3;
    int bc = blockIdx.x;
    int u0 = bc * 16;
    int m0 = wid * 16;

    // per-lane bias registers (combined where possible)
    float bA_rz[2][2][2], bA_in[2][2], bA_hn[2][2];
    float bB_rz[2][2][2], bB_in[2][2], bB_hn[2][2];
#pragma unroll
    for (int un = 0; un < 2; un++)
#pragma unroll
        for (int q = 0; q < 2; q++) {
            int j = u0 + un * 8 + 2 * tg + q;
            bA_rz[0][un][q] = bih0[j] + bhh0[j];
            bA_rz[1][un][q] = bih0[512 + j] + bhh0[512 + j];
            bA_in[un][q] = bih0[1024 + j]; bA_hn[un][q] = bhh0[1024 + j];
            bB_rz[0][un][q] = bih1[j] + bhh1[j];
            bB_rz[1][un][q] = bih1[512 + j] + bhh1[512 + j];
            bB_in[un][q] = bih1[1024 + j]; bB_hn[un][q] = bhh1[1024 + j];
        }

    float h0p[2][4], h1p[2][4];
#pragma unroll
    for (int un = 0; un < 2; un++)
#pragma unroll
        for (int c = 0; c < 4; c++) { h0p[un][c] = 0.f; h1p[un][c] = 0.f; }

    unsigned bar_gen = 0;

    for (int t = 0; t < Lsz; t++) {
        int s = t & 1;

        // ================= PHASE A: gh0 = h0_prev @ Whh0^T, then h0 update ====
        float acc[6][4];
#pragma unroll
        for (int nt = 0; nt < 6; nt++)
#pragma unroll
            for (int i = 0; i < 4; i++) acc[nt][i] = 0.f;

        for (int kc = 0; kc < Hsz; kc += 64) {
            __syncthreads();
#pragma unroll
            for (int i = 0; i < 4; i++) {
                int idx = tid + 256 * i; int arow = idx >> 3, kq = idx & 7;
                size_t go = (size_t)arow * Hsz + kc + kq * 8;
                *(uint4*)&A0h[arow * APITCH + kq * 8] = __ldcg((const uint4*)&g_h0hi[s][go]);
                *(uint4*)&A0l[arow * APITCH + kq * 8] = __ldcg((const uint4*)&g_h0lo[s][go]);
            }
#pragma unroll
            for (int i = 0; i < 2; i++) {
                int idx = tid + 256 * i;
                if (idx < 384) {
                    int wr = idx >> 3, kq = idx & 7;
                    int gate = wr >> 4, jl = wr & 15;
                    size_t go = (size_t)(gate * 512 + u0 + jl) * Hsz + kc + kq * 8;
                    *(uint4*)&W1h[wr * APITCH + kq * 8] = *(const uint4*)&g_Wbh[0][go];
                    *(uint4*)&W1l[wr * APITCH + kq * 8] = *(const uint4*)&g_Wbl[0][go];
                }
            }
            __syncthreads();
#pragma unroll
            for (int kk = 0; kk < 4; kk++) {
                int kb = kk * 16 + 2 * tg;
                int r0 = (m0 + g) * APITCH + kb;
                unsigned ah[4], al[4];
                ah[0] = SMU(A0h, r0); ah[1] = SMU(A0h, r0 + 8 * APITCH);
                ah[2] = SMU(A0h, r0 + 8); ah[3] = SMU(A0h, r0 + 8 * APITCH + 8);
                al[0] = SMU(A0l, r0); al[1] = SMU(A0l, r0 + 8 * APITCH);
                al[2] = SMU(A0l, r0 + 8); al[3] = SMU(A0l, r0 + 8 * APITCH + 8);
#pragma unroll
                for (int nt = 0; nt < 6; nt++) {
                    int wo = ((nt >> 1) * 16 + (nt & 1) * 8 + g) * APITCH + kb;
                    unsigned bh[2] = { SMU(W1h, wo), SMU(W1h, wo + 8) };
                    unsigned bl[2] = { SMU(W1l, wo), SMU(W1l, wo + 8) };
                    mma16816(acc[nt], ah, bh);
                    mma16816(acc[nt], al, bh);
                    mma16816(acc[nt], ah, bl);
                }
            }
        }

        // epilogue layer 0
#pragma unroll
        for (int un = 0; un < 2; un++) {
            int j0 = u0 + un * 8 + 2 * tg;
#pragma unroll
            for (int rh = 0; rh < 2; rh++) {
                int row = m0 + g + rh * 8;
                const float* gib = g_gi0 + ((size_t)t * Bsz + row) * G3;
                float2 gr = *(const float2*)(gib + j0);
                float2 gz = *(const float2*)(gib + 512 + j0);
                float2 gn = *(const float2*)(gib + 1024 + j0);
                float hq[2];
#pragma unroll
                for (int q = 0; q < 2; q++) {
                    int c = rh * 2 + q;
                    float gvr = (q ? gr.y : gr.x) + acc[0 + un][c] + bA_rz[0][un][q];
                    float gvz = (q ? gz.y : gz.x) + acc[2 + un][c] + bA_rz[1][un][q];
                    float r  = 1.0f / (1.0f + expf(-gvr));
                    float zg = 1.0f / (1.0f + expf(-gvz));
                    float n  = tanhf((q ? gn.y : gn.x) + bA_in[un][q] + r * (acc[4 + un][c] + bA_hn[un][q]));
                    float h  = (1.0f - zg) * n + zg * h0p[un][c];
                    h0p[un][c] = h; hq[q] = h;
                }
                bf16 h0b, l0b, h1b, l1b;
                bf16split(hq[0], h0b, l0b); bf16split(hq[1], h1b, l1b);
                unsigned phi = (unsigned)__bfloat16_as_ushort(h0b) | ((unsigned)__bfloat16_as_ushort(h1b) << 16);
                unsigned plo = (unsigned)__bfloat16_as_ushort(l0b) | ((unsigned)__bfloat16_as_ushort(l1b) << 16);
                __stcg((unsigned*)&g_h0hi[s ^ 1][row * Hsz + j0], phi);
                __stcg((unsigned*)&g_h0lo[s ^ 1][row * Hsz + j0], plo);
            }
        }

        // grid barrier
        bar_gen++;
        __syncthreads();
        if (tid == 0) {
            __threadfence();
            atomicAdd(&g_barcnt, 1u);
            while (*((volatile unsigned*)&g_barcnt) < bar_gen * NBLK) __nanosleep(32);
        }
        __syncthreads();

        // ===== PHASE B: gi1 = h0_cur @ Wih1^T ; gh1 = h1_prev @ Whh1^T =====
        float acci[6][4], acch[6][4];
#pragma unroll
        for (int nt = 0; nt < 6; nt++)
#pragma unroll
            for (int i = 0; i < 4; i++) { acci[nt][i] = 0.f; acch[nt][i] = 0.f; }

        for (int kc = 0; kc < Hsz; kc += 64) {
            __syncthreads();
#pragma unroll
            for (int i = 0; i < 4; i++) {
                int idx = tid + 256 * i; int arow = idx >> 3, kq = idx & 7;
                size_t go = (size_t)arow * Hsz + kc + kq * 8;
                int so = arow * APITCH + kq * 8;
                *(uint4*)&A0h[so] = __ldcg((const uint4*)&g_h0hi[s ^ 1][go]);
                *(uint4*)&A0l[so] = __ldcg((const uint4*)&g_h0lo[s ^ 1][go]);
                *(uint4*)&A1h[so] = __ldcg((const uint4*)&g_h1hi[s][go]);
                *(uint4*)&A1l[so] = __ldcg((const uint4*)&g_h1lo[s][go]);
            }
#pragma unroll
            for (int i = 0; i < 2; i++) {
                int idx = tid + 256 * i;
                if (idx < 384) {
                    int wr = idx >> 3, kq = idx & 7;
                    int gate = wr >> 4, jl = wr & 15;
                    size_t go = (size_t)(gate * 512 + u0 + jl) * Hsz + kc + kq * 8;
                    int so = wr * APITCH + kq * 8;
                    *(uint4*)&W1h[so] = *(const uint4*)&g_Wbh[1][go];
                    *(uint4*)&W1l[so] = *(const uint4*)&g_Wbl[1][go];
                    *(uint4*)&W2h[so] = *(const uint4*)&g_Wbh[2][go];
                    *(uint4*)&W2l[so] = *(const uint4*)&g_Wbl[2][go];
                }
            }
            __syncthreads();
#pragma unroll
            for (int kk = 0; kk < 4; kk++) {
                int kb = kk * 16 + 2 * tg;
                int r0 = (m0 + g) * APITCH + kb;
                unsigned a0h[4], a0l[4], a1h[4], a1l[4];
                a0h[0] = SMU(A0h, r0); a0h[1] = SMU(A0h, r0 + 8 * APITCH);
                a0h[2] = SMU(A0h, r0 + 8); a0h[3] = SMU(A0h, r0 + 8 * APITCH + 8);
                a0l[0] = SMU(A0l, r0); a0l[1] = SMU(A0l, r0 + 8 * APITCH);
                a0l[2] = SMU(A0l, r0 + 8); a0l[3] = SMU(A0l, r0 + 8 * APITCH + 8);
                a1h[0] = SMU(A1h, r0); a1h[1] = SMU(A1h, r0 + 8 * APITCH);
                a1h[2] = SMU(A1h, r0 + 8); a1h[3] = SMU(A1h, r0 + 8 * APITCH + 8);
                a1l[0] = SMU(A1l, r0); a1l[1] = SMU(A1l, r0 + 8 * APITCH);
                a1l[2] = SMU(A1l, r0 + 8); a1l[3] = SMU(A1l, r0 + 8 * APITCH + 8);
#pragma unroll
                for (int nt = 0; nt < 6; nt++) {
                    int wo = ((nt >> 1) * 16 + (nt & 1) * 8 + g) * APITCH + kb;
                    unsigned b1h[2] = { SMU(W1h, wo), SMU(W1h, wo + 8) };
                    unsigned b1l[2] = { SMU(W1l, wo), SMU(W1l, wo + 8) };
                    unsigned b2h[2] = { SMU(W2h, wo), SMU(W2h, wo + 8) };
                    unsigned b2l[2] = { SMU(W2l, wo), SMU(W2l, wo + 8) };
                    mma16816(acci[nt], a0h, b1h);
                    mma16816(acci[nt], a0l, b1h);
                    mma16816(acci[nt], a0h, b1l);
                    mma16816(acch[nt], a1h, b2h);
                    mma16816(acch[nt], a1l, b2h);
                    mma16816(acch[nt], a1h, b2l);
                }
            }
        }

        // epilogue layer 1
#pragma unroll
        for (int un = 0; un < 2; un++) {
            int j0 = u0 + un * 8 + 2 * tg;
#pragma unroll
            for (int rh = 0; rh < 2; rh++) {
                int row = m0 + g + rh * 8;
                float hq[2];
#pragma unroll
                for (int q = 0; q < 2; q++) {
                    int c = rh * 2 + q;
                    float gvr = acci[0 + un][c] + acch[0 + un][c] + bB_rz[0][un][q];
                    float gvz = acci[2 + un][c] + acch[2 + un][c] + bB_rz[1][un][q];
                    float r  = 1.0f / (1.0f + expf(-gvr));
                    float zg = 1.0f / (1.0f + expf(-gvz));
                    float n  = tanhf(acci[4 + un][c] + bB_in[un][q] + r * (acch[4 + un][c] + bB_hn[un][q]));
                    float h  = (1.0f - zg) * n + zg * h1p[un][c];
                    h1p[un][c] = h; hq[q] = h;
                }
                bf16 h0b, l0b, h1b, l1b;
                bf16split(hq[0], h0b, l0b); bf16split(hq[1], h1b, l1b);
                unsigned phi = (unsigned)__bfloat16_as_ushort(h0b) | ((unsigned)__bfloat16_as_ushort(h1b) << 16);
                unsigned plo = (unsigned)__bfloat16_as_ushort(l0b) | ((unsigned)__bfloat16_as_ushort(l1b) << 16);
                __stcg((unsigned*)&g_h1hi[s ^ 1][row * Hsz + j0], phi);
                __stcg((unsigned*)&g_h1lo[s ^ 1][row * Hsz + j0], plo);
                __stcg((float2*)&g_Ys[((size_t)t * Bsz + row) * Hsz + j0], make_float2(hq[0], hq[1]));
            }
        }

        // grid barrier
        bar_gen++;
        __syncthreads();
        if (tid == 0) {
            __threadfence();
            atomicAdd(&g_barcnt, 1u);
            while (*((volatile unsigned*)&g_barcnt) < bar_gen * NBLK) __nanosleep(32);
        }
        __syncthreads();
    }
}

// ---------------- output projection + inverse RevIN (validated round-11) ----
__global__ void __launch_bounds__(256)
outproj_kernel(const float* __restrict__ Wout, const float* __restrict__ bout,
               const float* __restrict__ w_o, const float* __restrict__ b_o,
               const float* __restrict__ w_c, const float* __restrict__ b_c,
               float* __restrict__ out)
{
    __shared__ float As[32][68];
    __shared__ float Ws[32][81];

    int r0  = blockIdx.x * 64;
    int tid = threadIdx.x;
    int tmr = tid & 15;
    int tcc = tid >> 4;

    int la_r = tid >> 2;
    int la_k = (tid & 3) * 8;

    float acc[4][5];
#pragma unroll
    for (int j = 0; j < 4; j++)
#pragma unroll
        for (int i = 0; i < 5; i++) acc[j][i] = 0.f;

    for (int kc = 0; kc < Hsz; kc += 32) {
        float4 a0 = *(const float4*)(g_Ys + (size_t)(r0 + la_r) * Hsz + kc + la_k);
        float4 a1 = *(const float4*)(g_Ys + (size_t)(r0 + la_r) * Hsz + kc + la_k + 4);
        As[la_k + 0][la_r] = a0.x; As[la_k + 1][la_r] = a0.y;
        As[la_k + 2][la_r] = a0.z; As[la_k + 3][la_r] = a0.w;
        As[la_k + 4][la_r] = a1.x; As[la_k + 5][la_r] = a1.y;
        As[la_k + 6][la_r] = a1.z; As[la_k + 7][la_r] = a1.w;
        for (int i = tid; i < 640; i += 256) {
            int n = i >> 3;
            int k = (i & 7) * 4;
            float4 wv = *(const float4*)(Wout + (size_t)n * Hsz + kc + k);
            Ws[k + 0][n] = wv.x; Ws[k + 1][n] = wv.y;
            Ws[k + 2][n] = wv.z; Ws[k + 3][n] = wv.w;
        }
        __syncthreads();
#pragma unroll
        for (int kk = 0; kk < 32; kk++) {
            float4 av = *(const float4*)&As[kk][4 * tmr];
            float a[4] = {av.x, av.y, av.z, av.w};
#pragma unroll
            for (int i = 0; i < 5; i++) {
                float bv = Ws[kk][5 * tcc + i];
#pragma unroll
                for (int j = 0; j < 4; j++) acc[j][i] += a[j] * bv;
            }
        }
        __syncthreads();
    }

    const size_t COV_OFF = (size_t)Bsz * Lsz * 16;
#pragma unroll
    for (int j = 0; j < 4; j++) {
        int rr   = r0 + 4 * tmr + j;
        int bsmp = rr & 127;
        int tt   = rr >> 7;
#pragma unroll
        for (int i = 0; i < 5; i++) {
            int cc  = 5 * tcc + i;
            float v = acc[j][i] + bout[cc];
            if (cc < 16) {
                int c = cc;
                float res = ((v - b_o[c]) / w_o[c]) * (g_osd[bsmp * 16 + c] + EPSF) + g_om[bsmp * 16 + c];
                out[((size_t)bsmp * Lsz + tt) * 16 + c] = res;
            } else {
                int c = cc - 16;
                float res = ((v - b_c[c]) / w_c[c]) * (g_csd[bsmp * 64 + c] + EPSF) + g_cm[bsmp * 64 + c];
                out[COV_OFF + ((size_t)bsmp * Lsz + tt) * 64 + c] = res;
            }
        }
    }
}

// ---------------- launch ----------------
extern "C" void kernel_launch(void* const* d_in, const int* in_sizes, int n_in,
                              void* d_out, int out_size)
{
    const float* cov  = (const float*)d_in[0];
    const float* tre  = (const float*)d_in[1];
    const float* outc = (const float*)d_in[2];
    const float* Wih0 = (const float*)d_in[3];
    const float* Whh0 = (const float*)d_in[4];
    const float* bih0 = (const float*)d_in[5];
    const float* bhh0 = (const float*)d_in[6];
    const float* Wih1 = (const float*)d_in[7];
    const float* Whh1 = (const float*)d_in[8];
    const float* bih1 = (const float*)d_in[9];
    const float* bhh1 = (const float*)d_in[10];
    const float* Wout = (const float*)d_in[11];
    const float* bout = (const float*)d_in[12];
    const float* w_t  = (const float*)d_in[13];
    const float* b_t  = (const float*)d_in[14];
    const float* w_o  = (const float*)d_in[15];
    const float* b_o  = (const float*)d_in[16];
    const float* w_c  = (const float*)d_in[17];
    const float* b_c  = (const float*)d_in[18];

    const int SMEM = (4 * 128 * APITCH + 4 * 48 * APITCH) * (int)sizeof(bf16);
    cudaFuncSetAttribute(rnn_kernel, cudaFuncAttributeMaxDynamicSharedMemorySize, SMEM);

    revin_kernel<<<Bsz, ICH>>>(cov, tre, outc, w_t, b_t, w_o, b_o, w_c, b_c);
    wsplit0_kernel<<<(G3 * ICH + 255) / 256, 256>>>(Wih0);
    wsplitB_kernel<<<(G3 * Hsz + 255) / 256, 256>>>(Whh0, 0);
    wsplitB_kernel<<<(G3 * Hsz + 255) / 256, 256>>>(Wih1, 1);
    wsplitB_kernel<<<(G3 * Hsz + 255) / 256, 256>>>(Whh1, 2);
    init_kernel<<<(Bsz * Hsz / 2 + 255) / 256, 256>>>();
    gi0_kernel<<<dim3(16, 2, Lsz), 128>>>();
    rnn_kernel<<<NBLK, 256, SMEM>>>(bih0, bhh0, bih1, bhh1);
    outproj_kernel<<<(Bsz * Lsz) / 64, 256>>>(Wout, bout, w_o, b_o, w_c, b_c, (float*)d_out);
}

// round 16
// speedup vs baseline: 2.8346x; 2.8346x over previous
#include <cuda_runtime.h>
#include <cuda_bf16.h>
#include <math.h>

#define Bsz 128
#define Lsz 512
#define Hsz 512
#define G3  1536
#define ICH 96
#define EPSF 1e-5f
#define NBLK 128
#define WP 520           // resident weight pitch (bf16 elems)
#define AP 72            // A-stage pitch (bf16 elems)

typedef __nv_bfloat16 bf16;

// ---------------- static device scratch ----------------
__device__ bf16  g_Xhi[(size_t)Lsz * Bsz * ICH];
__device__ bf16  g_Xlo[(size_t)Lsz * Bsz * ICH];
__device__ bf16  g_Wihi[(size_t)G3 * ICH];        // Wih0 split
__device__ bf16  g_Wilo[(size_t)G3 * ICH];
__device__ bf16  g_Wbh[3][(size_t)G3 * Hsz];      // 0:Whh0 1:Wih1 2:Whh1 (hi)
__device__ bf16  g_Wbl[3][(size_t)G3 * Hsz];      // (lo)
__device__ float g_gi0[(size_t)Lsz * Bsz * G3];   // X @ Wih0^T (no bias)
__device__ float g_Ys [(size_t)Lsz * Bsz * Hsz];  // h1 sequence [t][b][512]
__device__ bf16  g_h0hi[2][Bsz * Hsz];
__device__ bf16  g_h0lo[2][Bsz * Hsz];
__device__ bf16  g_h1hi[2][Bsz * Hsz];
__device__ bf16  g_h1lo[2][Bsz * Hsz];
__device__ float g_om[Bsz * 16], g_osd[Bsz * 16];
__device__ float g_cm[Bsz * 64], g_csd[Bsz * 64];
__device__ unsigned g_barcnt;

// ---------------- helpers ----------------
__device__ __forceinline__ void mma16816(float d[4], const unsigned a[4], const unsigned b0, const unsigned b1) {
    asm volatile(
        "mma.sync.aligned.m16n8k16.row.col.f32.bf16.bf16.f32 "
        "{%0,%1,%2,%3}, {%4,%5,%6,%7}, {%8,%9}, {%0,%1,%2,%3};\n"
        : "+f"(d[0]), "+f"(d[1]), "+f"(d[2]), "+f"(d[3])
        : "r"(a[0]), "r"(a[1]), "r"(a[2]), "r"(a[3]), "r"(b0), "r"(b1));
}
__device__ __forceinline__ void ldm4(unsigned f[4], unsigned addr) {
    asm volatile("ldmatrix.sync.aligned.m8n8.x4.shared.b16 {%0,%1,%2,%3}, [%4];"
                 : "=r"(f[0]), "=r"(f[1]), "=r"(f[2]), "=r"(f[3]) : "r"(addr));
}
__device__ __forceinline__ void bf16split(float v, bf16& hi, bf16& lo) {
    hi = __float2bfloat16(v);
    lo = __float2bfloat16(v - __bfloat162float(hi));
}
#define SMU(P, o) (*(const unsigned*)&(P)[(o)])
#define CPASYNC16(dst, src) asm volatile("cp.async.cg.shared.global [%0], [%1], 16;\n" :: "r"(dst), "l"(src))
#define CPCOMMIT()          asm volatile("cp.async.commit_group;\n")
#define CPWAIT1()           asm volatile("cp.async.wait_group 1;\n")
#define CPWAIT0()           asm volatile("cp.async.wait_group 0;\n")

// ---------------- RevIN normalize + split-pack ----------------
__global__ void revin_kernel(const float* __restrict__ cov,
                             const float* __restrict__ tre,
                             const float* __restrict__ outc,
                             const float* __restrict__ w_t, const float* __restrict__ b_t,
                             const float* __restrict__ w_o, const float* __restrict__ b_o,
                             const float* __restrict__ w_c, const float* __restrict__ b_c)
{
    int b  = blockIdx.x;
    int ch = threadIdx.x;            // 0..95
    const float* src; int c, nch; float w, bb;
    if (ch < 16)      { c = ch;      src = tre  + (size_t)b * Lsz * 16 + c; nch = 16; w = w_t[c]; bb = b_t[c]; }
    else if (ch < 32) { c = ch - 16; src = outc + (size_t)b * Lsz * 16 + c; nch = 16; w = w_o[c]; bb = b_o[c]; }
    else              { c = ch - 32; src = cov  + (size_t)b * Lsz * 64 + c; nch = 64; w = w_c[c]; bb = b_c[c]; }

    float sum = 0.f, sq = 0.f;
    for (int l = 0; l < Lsz; l++) {
        float v = src[(size_t)l * nch];
        sum += v; sq += v * v;
    }
    float m   = sum * (1.0f / Lsz);
    float var = (sq - sum * m) * (1.0f / (Lsz - 1));
    float s   = sqrtf(var);

    if (ch >= 16 && ch < 32) { g_om[b * 16 + c] = m; g_osd[b * 16 + c] = s; }
    else if (ch >= 32)       { g_cm[b * 64 + c] = m; g_csd[b * 64 + c] = s; }

    float inv = 1.0f / (s + EPSF);
    for (int l = 0; l < Lsz; l++) {
        float v = src[(size_t)l * nch];
        float x = (v - m) * inv * w + bb;
        bf16 hi, lo; bf16split(x, hi, lo);
        size_t o = ((size_t)l * Bsz + b) * ICH + ch;
        g_Xhi[o] = hi; g_Xlo[o] = lo;
    }
}

// ---------------- weight splitting ----------------
__global__ void wsplit0_kernel(const float* __restrict__ W)
{
    int i = blockIdx.x * blockDim.x + threadIdx.x;
    if (i < G3 * ICH) { bf16 h, l; bf16split(W[i], h, l); g_Wihi[i] = h; g_Wilo[i] = l; }
}
__global__ void wsplitB_kernel(const float* __restrict__ W, int m)
{
    int i = blockIdx.x * blockDim.x + threadIdx.x;
    if (i < G3 * Hsz) { bf16 h, l; bf16split(W[i], h, l); g_Wbh[m][i] = h; g_Wbl[m][i] = l; }
}

// ---------------- init: zero BOTH h slots + barrier counter ----------------
// (Round-14 bug: only slot 0 was zeroed; slot 1 carried h1(511) from the
//  previous call into tick 1's read of h1(-1) -> cross-call divergence.)
__global__ void init_kernel()
{
    int i = blockIdx.x * blockDim.x + threadIdx.x;
    if (i < Bsz * Hsz / 2) {
        ((unsigned*)g_h0hi[0])[i] = 0u; ((unsigned*)g_h0lo[0])[i] = 0u;
        ((unsigned*)g_h1hi[0])[i] = 0u; ((unsigned*)g_h1lo[0])[i] = 0u;
        ((unsigned*)g_h0hi[1])[i] = 0u; ((unsigned*)g_h0lo[1])[i] = 0u;
        ((unsigned*)g_h1hi[1])[i] = 0u; ((unsigned*)g_h1lo[1])[i] = 0u;
    }
    if (i == 0) g_barcnt = 0u;
}

// ---------------- gi0 = X @ Wih0^T (mma, bf16 split) ----------------
__global__ void __launch_bounds__(128)
gi0_kernel()
{
    __shared__ bf16 Xs[2][64][104];

    int tid = threadIdx.x;
    int wid = tid >> 5, lane = tid & 31;
    int g = lane >> 2, tg = lane & 3;
    int n0 = blockIdx.x * 96;
    int m0 = blockIdx.y * 64;
    int t  = blockIdx.z;

    for (int i = 0; i < 6; i++) {
        int idx = tid + 128 * i;
        int row = idx / 12, kq = idx % 12;
        size_t go = ((size_t)t * Bsz + m0 + row) * ICH + kq * 8;
        *(uint4*)&Xs[0][row][kq * 8] = *(const uint4*)&g_Xhi[go];
        *(uint4*)&Xs[1][row][kq * 8] = *(const uint4*)&g_Xlo[go];
    }
    __syncthreads();

    float acc[12][4];
#pragma unroll
    for (int nt = 0; nt < 12; nt++)
#pragma unroll
        for (int i = 0; i < 4; i++) acc[nt][i] = 0.f;

    int r0 = wid * 16 + g;
#pragma unroll
    for (int kk = 0; kk < 6; kk++) {
        int kb = kk * 16 + 2 * tg;
        unsigned ah[4], al[4];
        ah[0] = SMU(Xs[0][r0], kb);     ah[1] = SMU(Xs[0][r0 + 8], kb);
        ah[2] = SMU(Xs[0][r0], kb + 8); ah[3] = SMU(Xs[0][r0 + 8], kb + 8);
        al[0] = SMU(Xs[1][r0], kb);     al[1] = SMU(Xs[1][r0 + 8], kb);
        al[2] = SMU(Xs[1][r0], kb + 8); al[3] = SMU(Xs[1][r0 + 8], kb + 8);
#pragma unroll
        for (int nt = 0; nt < 12; nt++) {
            size_t wr = (size_t)(n0 + nt * 8 + g) * ICH + kk * 16 + 2 * tg;
            mma16816(acc[nt], ah, SMU(g_Wihi, wr), SMU(g_Wihi, wr + 8));
            mma16816(acc[nt], al, SMU(g_Wihi, wr), SMU(g_Wihi, wr + 8));
            mma16816(acc[nt], ah, SMU(g_Wilo, wr), SMU(g_Wilo, wr + 8));
        }
    }

#pragma unroll
    for (int nt = 0; nt < 12; nt++) {
        int b0  = m0 + r0;
        int col = n0 + nt * 8 + 2 * tg;
        *(float2*)&g_gi0[((size_t)t * Bsz + b0) * G3 + col]     = make_float2(acc[nt][0], acc[nt][1]);
        *(float2*)&g_gi0[((size_t)t * Bsz + b0 + 8) * G3 + col] = make_float2(acc[nt][2], acc[nt][3]);
    }
}

// ---------------- persistent RNN kernel ----------------
// 128 blocks x 128 threads. Block = (unit-group ug of 8 units, m-half of 64 rows).
// Per tick k: layer0 of step k and layer1 of step k-1, sharing the h0(k-1) stage.
#define WELE (6 * 24 * WP)     // 74880 elems resident weights
__global__ void __launch_bounds__(128, 1)
rnn_kernel(const float* __restrict__ bih0, const float* __restrict__ bhh0,
           const float* __restrict__ bih1, const float* __restrict__ bhh1)
{
    extern __shared__ bf16 sm[];
    bf16* Wres = sm;                    // [6][24][WP]  (mat*2+part)
    // A-stage: [2 buf][4 comp][64 rows][AP] at sm + WELE

    int tid = threadIdx.x;
    int wid = tid >> 5, lane = tid & 31;
    int g = lane >> 2, tg = lane & 3;
    int bc = blockIdx.x;
    int ug = bc & 63, mh = bc >> 6;
    int u0 = ug * 8;
    int m0b = mh * 64;
    int mrow = m0b + wid * 16;
    unsigned smbase = (unsigned)__cvta_generic_to_shared(sm);

    // ---- stage resident weights (k-permuted for LDS.64 B-fragments) ----
    {
        const bf16* wsrc[6] = { g_Wbh[0], g_Wbl[0], g_Wbh[1], g_Wbl[1], g_Wbh[2], g_Wbl[2] };
#pragma unroll 1
        for (int p = tid; p < 6 * 24 * 256; p += 128) {
            int w   = p / (24 * 256);
            int rem = p - w * (24 * 256);
            int rr  = rem >> 8;            // 0..23  (gate*8 + jl)
            int kp  = rem & 255;           // k-pair
            int gate = rr >> 3, jl = rr & 7;
            unsigned v = *(const unsigned*)(wsrc[w] + (size_t)(gate * 512 + u0 + jl) * Hsz + kp * 2);
            int k  = kp * 2;
            int ps = kp & 7;
            int pp = ((ps & 3) << 1) | (ps >> 2);
            *(unsigned*)&Wres[(w * 24 + rr) * WP + (k & ~15) + pp * 2] = v;
        }
    }

    // per-lane bias registers
    float e0r[2], e0z[2], e0in[2], e0hn[2];
    float e1r[2], e1z[2], e1in[2], e1hn[2];
#pragma unroll
    for (int q = 0; q < 2; q++) {
        int j = u0 + 2 * tg + q;
        e0r[q]  = bih0[j] + bhh0[j];
        e0z[q]  = bih0[512 + j] + bhh0[512 + j];
        e0in[q] = bih0[1024 + j]; e0hn[q] = bhh0[1024 + j];
        e1r[q]  = bih1[j] + bhh1[j];
        e1z[q]  = bih1[512 + j] + bhh1[512 + j];
        e1in[q] = bih1[1024 + j]; e1hn[q] = bhh1[1024 + j];
    }
    __syncthreads();

    float h0p[4], h1p[4];
#pragma unroll
    for (int c = 0; c < 4; c++) { h0p[c] = 0.f; h1p[c] = 0.f; }

    // ldmatrix lane address pieces (elems)
    int lrow = lane & 15;
    int lkof = (lane >> 4) * 8;

    unsigned bar = 0;

    for (int k = 0; k <= Lsz; k++) {
        int sl = k & 1, ws = sl ^ 1;
        const bf16* srcs[4] = { g_h0hi[sl], g_h0lo[sl], g_h1hi[sl], g_h1lo[sl] };

        // prefetch gi0 for t=k (clamped) — consumed in epilogue0
        int tc = (k < Lsz) ? k : (Lsz - 1);
        const float* gib = g_gi0 + ((size_t)tc * Bsz + mrow + g) * G3 + u0 + 2 * tg;
        float2 gr0 = __ldcg((const float2*)(gib));
        float2 gz0 = __ldcg((const float2*)(gib + 512));
        float2 gn0 = __ldcg((const float2*)(gib + 1024));
        float2 gr1 = __ldcg((const float2*)(gib + 8 * G3));
        float2 gz1 = __ldcg((const float2*)(gib + 8 * G3 + 512));
        float2 gn1 = __ldcg((const float2*)(gib + 8 * G3 + 1024));

        float acc0[3][4], acci[3][4], acch[3][4];
#pragma unroll
        for (int nt = 0; nt < 3; nt++)
#pragma unroll
            for (int i = 0; i < 4; i++) { acc0[nt][i] = 0.f; acci[nt][i] = 0.f; acch[nt][i] = 0.f; }

        // issue chunk 0
#pragma unroll
        for (int i = 0; i < 16; i++) {
            int idx  = tid + 128 * i;
            int comp = idx >> 9, r = (idx >> 3) & 63, c16 = idx & 7;
            const bf16* sp = srcs[comp] + (size_t)(m0b + r) * Hsz + c16 * 8;
            unsigned dst = smbase + (unsigned)((WELE + ((comp) * 64 + r) * AP + c16 * 8) * 2);
            CPASYNC16(dst, sp);
        }
        CPCOMMIT();

        for (int c = 0; c < 8; c++) {
            if (c < 7) {   // issue chunk c+1 into buf (c+1)&1
                int nb = (c + 1) & 1;
#pragma unroll
                for (int i = 0; i < 16; i++) {
                    int idx  = tid + 128 * i;
                    int comp = idx >> 9, r = (idx >> 3) & 63, c16 = idx & 7;
                    const bf16* sp = srcs[comp] + (size_t)(m0b + r) * Hsz + (c + 1) * 64 + c16 * 8;
                    unsigned dst = smbase + (unsigned)((WELE + ((nb * 4 + comp) * 64 + r) * AP + c16 * 8) * 2);
                    CPASYNC16(dst, sp);
                }
                CPCOMMIT();
                CPWAIT1();
            } else {
                CPWAIT0();
            }
            __syncthreads();

            int buf = c & 1;
            unsigned ab[4];
#pragma unroll
            for (int comp = 0; comp < 4; comp++)
                ab[comp] = smbase + (unsigned)((WELE + ((buf * 4 + comp) * 64 + wid * 16 + lrow) * AP + lkof) * 2);
            int wko = c * 64;   // weight k elem offset for this chunk

#pragma unroll
            for (int kk = 0; kk < 4; kk++) {
                unsigned f0h[4], f0l[4], f1h[4], f1l[4];
                ldm4(f0h, ab[0] + kk * 32);
                ldm4(f0l, ab[1] + kk * 32);
                ldm4(f1h, ab[2] + kk * 32);
                ldm4(f1l, ab[3] + kk * 32);
#pragma unroll
                for (int nt = 0; nt < 3; nt++) {
                    int ro = (nt * 8 + g) * WP + wko + kk * 16 + tg * 4;
                    uint2 b0h = *(const uint2*)&Wres[0 * 24 * WP + ro];
                    uint2 b0l = *(const uint2*)&Wres[1 * 24 * WP + ro];
                    uint2 b1h = *(const uint2*)&Wres[2 * 24 * WP + ro];
                    uint2 b1l = *(const uint2*)&Wres[3 * 24 * WP + ro];
                    uint2 b2h = *(const uint2*)&Wres[4 * 24 * WP + ro];
                    uint2 b2l = *(const uint2*)&Wres[5 * 24 * WP + ro];
                    mma16816(acc0[nt], f0h, b0h.x, b0h.y);
                    mma16816(acc0[nt], f0l, b0h.x, b0h.y);
                    mma16816(acc0[nt], f0h, b0l.x, b0l.y);
                    mma16816(acci[nt], f0h, b1h.x, b1h.y);
                    mma16816(acci[nt], f0l, b1h.x, b1h.y);
                    mma16816(acci[nt], f0h, b1l.x, b1l.y);
                    mma16816(acch[nt], f1h, b2h.x, b2h.y);
                    mma16816(acch[nt], f1l, b2h.x, b2h.y);
                    mma16816(acch[nt], f1h, b2l.x, b2l.y);
                }
            }
            __syncthreads();
        }

        // ---- epilogue layer 0 (step k) ----
        if (k < Lsz) {
#pragma unroll
            for (int rh = 0; rh < 2; rh++) {
                int row = mrow + g + rh * 8;
                float2 grv = rh ? gr1 : gr0;
                float2 gzv = rh ? gz1 : gz0;
                float2 gnv = rh ? gn1 : gn0;
                float hq[2];
#pragma unroll
                for (int q = 0; q < 2; q++) {
                    int c = rh * 2 + q;
                    float gvr = (q ? grv.y : grv.x) + acc0[0][c] + e0r[q];
                    float gvz = (q ? gzv.y : gzv.x) + acc0[1][c] + e0z[q];
                    float r  = 1.0f / (1.0f + expf(-gvr));
                    float zg = 1.0f / (1.0f + expf(-gvz));
                    float n  = tanhf((q ? gnv.y : gnv.x) + e0in[q] + r * (acc0[2][c] + e0hn[q]));
                    float h  = (1.0f - zg) * n + zg * h0p[c];
                    h0p[c] = h; hq[q] = h;
                }
                bf16 hh0, hl0, hh1, hl1;
                bf16split(hq[0], hh0, hl0); bf16split(hq[1], hh1, hl1);
                unsigned phi = (unsigned)__bfloat16_as_ushort(hh0) | ((unsigned)__bfloat16_as_ushort(hh1) << 16);
                unsigned plo = (unsigned)__bfloat16_as_ushort(hl0) | ((unsigned)__bfloat16_as_ushort(hl1) << 16);
                __stcg((unsigned*)&g_h0hi[ws][row * Hsz + u0 + 2 * tg], phi);
                __stcg((unsigned*)&g_h0lo[ws][row * Hsz + u0 + 2 * tg], plo);
            }
        }

        // ---- epilogue layer 1 (step k-1) ----
        if (k > 0) {
            int t1 = k - 1;
#pragma unroll
            for (int rh = 0; rh < 2; rh++) {
                int row = mrow + g + rh * 8;
                float hq[2];
#pragma unroll
                for (int q = 0; q < 2; q++) {
                    int c = rh * 2 + q;
                    float gvr = acci[0][c] + acch[0][c] + e1r[q];
                    float gvz = acci[1][c] + acch[1][c] + e1z[q];
                    float r  = 1.0f / (1.0f + expf(-gvr));
                    float zg = 1.0f / (1.0f + expf(-gvz));
                    float n  = tanhf(acci[2][c] + e1in[q] + r * (acch[2][c] + e1hn[q]));
                    float h  = (1.0f - zg) * n + zg * h1p[c];
                    h1p[c] = h; hq[q] = h;
                }
                bf16 hh0, hl0, hh1, hl1;
                bf16split(hq[0], hh0, hl0); bf16split(hq[1], hh1, hl1);
                unsigned phi = (unsigned)__bfloat16_as_ushort(hh0) | ((unsigned)__bfloat16_as_ushort(hh1) << 16);
                unsigned plo = (unsigned)__bfloat16_as_ushort(hl0) | ((unsigned)__bfloat16_as_ushort(hl1) << 16);
                __stcg((unsigned*)&g_h1hi[ws][row * Hsz + u0 + 2 * tg], phi);
                __stcg((unsigned*)&g_h1lo[ws][row * Hsz + u0 + 2 * tg], plo);
                __stcg((float2*)&g_Ys[((size_t)t1 * Bsz + row) * Hsz + u0 + 2 * tg], make_float2(hq[0], hq[1]));
            }
        }

        // ---- grid barrier ----
        if (k < Lsz) {
            bar++;
            __syncthreads();
            if (tid == 0) {
                __threadfence();
                atomicAdd(&g_barcnt, 1u);
                while (*((volatile unsigned*)&g_barcnt) < bar * NBLK) __nanosleep(32);
                __threadfence();
            }
            __syncthreads();
        }
    }
}

// ---------------- output projection + inverse RevIN ----------------
__global__ void __launch_bounds__(256)
outproj_kernel(const float* __restrict__ Wout, const float* __restrict__ bout,
               const float* __restrict__ w_o, const float* __restrict__ b_o,
               const float* __restrict__ w_c, const float* __restrict__ b_c,
               float* __restrict__ out)
{
    __shared__ float As[32][68];
    __shared__ float Ws[32][81];

    int r0  = blockIdx.x * 64;
    int tid = threadIdx.x;
    int tmr = tid & 15;
    int tcc = tid >> 4;

    int la_r = tid >> 2;
    int la_k = (tid & 3) * 8;

    float acc[4][5];
#pragma unroll
    for (int j = 0; j < 4; j++)
#pragma unroll
        for (int i = 0; i < 5; i++) acc[j][i] = 0.f;

    for (int kc = 0; kc < Hsz; kc += 32) {
        float4 a0 = *(const float4*)(g_Ys + (size_t)(r0 + la_r) * Hsz + kc + la_k);
        float4 a1 = *(const float4*)(g_Ys + (size_t)(r0 + la_r) * Hsz + kc + la_k + 4);
        As[la_k + 0][la_r] = a0.x; As[la_k + 1][la_r] = a0.y;
        As[la_k + 2][la_r] = a0.z; As[la_k + 3][la_r] = a0.w;
        As[la_k + 4][la_r] = a1.x; As[la_k + 5][la_r] = a1.y;
        As[la_k + 6][la_r] = a1.z; As[la_k + 7][la_r] = a1.w;
        for (int i = tid; i < 640; i += 256) {
            int n = i >> 3;
            int k = (i & 7) * 4;
            float4 wv = *(const float4*)(Wout + (size_t)n * Hsz + kc + k);
            Ws[k + 0][n] = wv.x; Ws[k + 1][n] = wv.y;
            Ws[k + 2][n] = wv.z; Ws[k + 3][n] = wv.w;
        }
        __syncthreads();
#pragma unroll
        for (int kk = 0; kk < 32; kk++) {
            float4 av = *(const float4*)&As[kk][4 * tmr];
            float a[4] = {av.x, av.y, av.z, av.w};
#pragma unroll
            for (int i = 0; i < 5; i++) {
                float bv = Ws[kk][5 * tcc + i];
#pragma unroll
                for (int j = 0; j < 4; j++) acc[j][i] += a[j] * bv;
            }
        }
        __syncthreads();
    }

    const size_t COV_OFF = (size_t)Bsz * Lsz * 16;
#pragma unroll
    for (int j = 0; j < 4; j++) {
        int rr   = r0 + 4 * tmr + j;
        int bsmp = rr & 127;
        int tt   = rr >> 7;
#pragma unroll
        for (int i = 0; i < 5; i++) {
            int cc  = 5 * tcc + i;
            float v = acc[j][i] + bout[cc];
            if (cc < 16) {
                int c = cc;
                float res = ((v - b_o[c]) / w_o[c]) * (g_osd[bsmp * 16 + c] + EPSF) + g_om[bsmp * 16 + c];
                out[((size_t)bsmp * Lsz + tt) * 16 + c] = res;
            } else {
                int c = cc - 16;
                float res = ((v - b_c[c]) / w_c[c]) * (g_csd[bsmp * 64 + c] + EPSF) + g_cm[bsmp * 64 + c];
                out[COV_OFF + ((size_t)bsmp * Lsz + tt) * 64 + c] = res;
            }
        }
    }
}

// ---------------- launch ----------------
extern "C" void kernel_launch(void* const* d_in, const int* in_sizes, int n_in,
                              void* d_out, int out_size)
{
    const float* cov  = (const float*)d_in[0];
    const float* tre  = (const float*)d_in[1];
    const float* outc = (const float*)d_in[2];
    const float* Wih0 = (const float*)d_in[3];
    const float* Whh0 = (const float*)d_in[4];
    const float* bih0 = (const float*)d_in[5];
    const float* bhh0 = (const float*)d_in[6];
    const float* Wih1 = (const float*)d_in[7];
    const float* Whh1 = (const float*)d_in[8];
    const float* bih1 = (const float*)d_in[9];
    const float* bhh1 = (const float*)d_in[10];
    const float* Wout = (const float*)d_in[11];
    const float* bout = (const float*)d_in[12];
    const float* w_t  = (const float*)d_in[13];
    const float* b_t  = (const float*)d_in[14];
    const float* w_o  = (const float*)d_in[15];
    const float* b_o  = (const float*)d_in[16];
    const float* w_c  = (const float*)d_in[17];
    const float* b_c  = (const float*)d_in[18];

    const int SMEM = (WELE + 2 * 4 * 64 * AP) * (int)sizeof(bf16);   // 223,488 B
    cudaFuncSetAttribute(rnn_kernel, cudaFuncAttributeMaxDynamicSharedMemorySize, SMEM);

    revin_kernel<<<Bsz, ICH>>>(cov, tre, outc, w_t, b_t, w_o, b_o, w_c, b_c);
    wsplit0_kernel<<<(G3 * ICH + 255) / 256, 256>>>(Wih0);
    wsplitB_kernel<<<(G3 * Hsz + 255) / 256, 256>>>(Whh0, 0);
    wsplitB_kernel<<<(G3 * Hsz + 255) / 256, 256>>>(Wih1, 1);
    wsplitB_kernel<<<(G3 * Hsz + 255) / 256, 256>>>(Whh1, 2);
    init_kernel<<<(Bsz * Hsz / 2 + 255) / 256, 256>>>();
    gi0_kernel<<<dim3(16, 2, Lsz), 128>>>();
    rnn_kernel<<<NBLK, 128, SMEM>>>(bih0, bhh0, bih1, bhh1);
    outproj_kernel<<<(Bsz * Lsz) / 64, 256>>>(Wout, bout, w_o, b_o, w_c, b_c, (float*)d_out);
}